// round 3
// baseline (speedup 1.0000x reference)
#include <cuda_runtime.h>
#include <cuda_bf16.h>
#include <math.h>

// Static shapes: B=2048, D=256, K = D/2-1 = 127.
// Output R[B, D, D] fp32 = 512 MiB. Nonzeros (all at even row/col):
//   R[p, 2i,   2i  ] =  cos(p*theta_i)            i in 0..K-1
//   R[p, 2i,   2i+2] = -sin(p*theta_i)            i in 0..K-1
//   R[p, 2i+2, 2i  ] =  sin(p*theta_i)            i in 0..K-1
//   R[p, 2K,   2K  ] =  cos(p*theta_{K-1})        (surviving overwrite)
// theta_i = 10000^(-2*(i-1)/D)

#define EMB_DIM 256
#define K_ITERS 127

// theta in double (then fp32) matches the reference fp32 phase to ~1 ulp;
// sinf/cosf do full argument reduction for |m| < ~2200.
__device__ __forceinline__ float rope_cos(int i, int p) {
    const double e = -2.0 * ((double)i - 1.0) / (double)EMB_DIM;
    const float theta = (float)exp(e * 9.210340371976184);  // ln(10000)
    return cosf((float)p * theta);
}
__device__ __forceinline__ float rope_sin(int i, int p) {
    const double e = -2.0 * ((double)i - 1.0) / (double)EMB_DIM;
    const float theta = (float)exp(e * 9.210340371976184);
    return sinf((float)p * theta);
}

// Value of R[p, r, col] for even r, even col (odd anything is zero).
__device__ __forceinline__ float rope_entry(int r, int col, int p) {
    const int d = col - r;
    if (d == 0) {
        int i = r >> 1;
        if (i > K_ITERS - 1) i = K_ITERS - 1;   // r = 2K -> cos(theta_{K-1})
        return rope_cos(i, p);
    }
    if (d == -2) {
        // sub-diagonal: row = 2i+2, col = 2i -> i = col/2 (0..126)
        return rope_sin(col >> 1, p);
    }
    if (d == 2) {
        // super-diagonal: row = 2i -> i = r/2, valid only for i <= K-1
        const int i = r >> 1;
        if (i <= K_ITERS - 1) return -rope_sin(i, p);
    }
    return 0.0f;
}

// One thread per float4 (16B). Total quads = 2048 * 256 * 64 = 33,554,432.
// Per matrix: 256 rows x 64 quads = 16384 quads.
__global__ void rope_fused_kernel(float4* __restrict__ out) {
    const int idx  = blockIdx.x * blockDim.x + threadIdx.x;
    const int p    = idx >> 14;          // quad / 16384
    const int rem  = idx & 16383;
    const int row  = rem >> 6;           // 0..255
    const int col4 = rem & 63;           // quad within row

    float4 v = make_float4(0.f, 0.f, 0.f, 0.f);

    if ((row & 1) == 0) {
        const int c0 = col4 << 2;        // first column of this quad (multiple of 4)
        // Nonzero columns for row r are r-2, r, r+2 (all even). Within this
        // quad only components .x (col c0) and .z (col c0+2) can be nonzero.
        const int dx = c0 - row;
        if (dx >= -2 && dx <= 2) v.x = rope_entry(row, c0, p);
        const int dz = dx + 2;
        if (dz >= -2 && dz <= 2) v.z = rope_entry(row, c0 + 2, p);
    }

    out[idx] = v;
}

extern "C" void kernel_launch(void* const* d_in, const int* in_sizes, int n_in,
                              void* d_out, int out_size) {
    (void)d_in; (void)in_sizes; (void)n_in; (void)out_size;

    // 33,554,432 quads / 256 threads = 131072 blocks.
    rope_fused_kernel<<<131072, 256, 0, 0>>>((float4*)d_out);
}

// round 4
// speedup vs baseline: 10.8230x; 10.8230x over previous
#include <cuda_runtime.h>
#include <cuda_bf16.h>
#include <math.h>

// Static shapes: B=2048, D=256, K = D/2-1 = 127.
// Output R[B, 256, 256] fp32 = 512 MiB. Nonzeros (even rows only):
//   row r: col r-2 -> sin(p*theta_{(r-2)/2})       (r >= 2)
//          col r   -> cos(p*theta_{min(r/2,126)})
//          col r+2 -> -sin(p*theta_{r/2})          (r/2 <= 126)
//   theta_i = 10000^(-2*(i-1)/256)
//
// One block per matrix p. Thread tid owns column-quad j = tid&63 and rows
// 4k + (tid>>6), k = 0..63. Its 64 stores are base + k*4096 (STG.128 imm
// offsets). Band quads are then patched by <=2 extra full-quad stores.

#define K_ITERS 127

__global__ __launch_bounds__(256) void rope_kernel(float4* __restrict__ out) {
    __shared__ float sc[K_ITERS];
    __shared__ float ss[K_ITERS];

    const int tid = threadIdx.x;
    const int p   = blockIdx.x;

    // Phase 1: per-matrix sin/cos table (127 heavy threads per block).
    if (tid < K_ITERS) {
        const double e = -2.0 * ((double)tid - 1.0) / 256.0;
        const float theta = (float)exp(e * 9.210340371976184);  // ln(10000)
        const float m = (float)p * theta;
        ss[tid] = sinf(m);
        sc[tid] = cosf(m);
    }
    __syncthreads();

    // Phase 2: stream zeros. Address = out + p*16384 + k*256 + tid.
    float4* base = out + ((size_t)p << 14) + tid;
    const float4 z = make_float4(0.f, 0.f, 0.f, 0.f);
#pragma unroll
    for (int k = 0; k < 64; k++) {
        base[k << 8] = z;   // STG.128 [Rbase + k*4096], zeros
    }

    // Phase 3: patch the band quads (complete quads, overwrite is safe:
    // same thread, same address -> program order).
    const int h = tid >> 6;     // row offset class 0..3
    const int j = tid & 63;     // column quad
    if (h == 0) {
        // row 4j, quad j: .x = cos_{2j}, .z = -sin_{2j}
        base[j << 8] = make_float4(sc[2 * j], 0.f, -ss[2 * j], 0.f);
        // row 4j+4, quad j: .z = sin_{2j+1}
        if (j <= 62)
            base[(j + 1) << 8] = make_float4(0.f, 0.f, ss[2 * j + 1], 0.f);
    } else if (h == 2) {
        // row 4j+2, quad j: .x = sin_{2j}, .z = cos_{min(2j+1,126)}
        int i = 2 * j + 1; if (i > K_ITERS - 1) i = K_ITERS - 1;
        base[j << 8] = make_float4(ss[2 * j], 0.f, sc[i], 0.f);
        // row 4j-2, quad j: .x = -sin_{2j-1}
        if (j >= 1)
            base[(j - 1) << 8] = make_float4(-ss[2 * j - 1], 0.f, 0.f, 0.f);
    }
}

extern "C" void kernel_launch(void* const* d_in, const int* in_sizes, int n_in,
                              void* d_out, int out_size) {
    (void)d_in; (void)in_sizes; (void)n_in; (void)out_size;
    rope_kernel<<<2048, 256, 0, 0>>>((float4*)d_out);
}

// round 5
// speedup vs baseline: 12.4990x; 1.1548x over previous
#include <cuda_runtime.h>
#include <cuda_bf16.h>
#include <math.h>

// Static shapes: B=2048, D=256, K = D/2-1 = 127. Output R[2048,256,256] fp32.
// Nonzeros (even rows r only):
//   col r-2 -> sin(p*theta_{(r-2)/2})    (r >= 2)
//   col r   -> cos(p*theta_{min(r/2,126)})
//   col r+2 -> -sin(p*theta_{r/2})       (r/2 <= 126)
// theta_i = 10000^(-2*(i-1)/256)
//
// Grid: 8192 blocks = 2048 matrices x 4 chunks. Chunk q owns row-groups
// kp in [16q, 16q+16) (each group = 4 rows = 256 quads). Thread tid = h*64+j
// writes quad (kp*256 + tid) for each kp in its chunk: 16 STG.128 of zeros,
// then <=2 patch STG.128 overwriting the near-diagonal quads (same thread,
// same address -> program order guarantees the patch wins).

#define K_ITERS 127

__global__ __launch_bounds__(256) void rope_kernel(float4* __restrict__ out) {
    // Table slice: indices i = off + t, t in [0,36), off = 2*k0 - 1.
    __shared__ float s_c[36];
    __shared__ float s_s[36];

    const int tid = threadIdx.x;
    const int p   = blockIdx.x >> 2;
    const int q   = blockIdx.x & 3;
    const int k0  = q << 4;              // first row-group of this chunk
    const int off = 2 * k0 - 1;

    // Phase 1a: table slice (2 warps of heavy math; overlaps with zeros below).
    if (tid < 36) {
        const int i = off + tid;
        if (i >= 0 && i < K_ITERS) {
            const double e = -2.0 * ((double)i - 1.0) / 256.0;
            const float theta = (float)exp(e * 9.210340371976184);  // ln(10000)
            const float m = (float)p * theta;
            s_s[tid] = sinf(m);
            s_c[tid] = cosf(m);
        }
    }

    // Phase 1b: stream zeros for this chunk (no dependence on the table).
    float4* mbase = out + ((size_t)p << 14) + tid;        // matrix base + tid
    float4* zbase = mbase + ((size_t)k0 << 8);            // chunk base
    const float4 z = make_float4(0.f, 0.f, 0.f, 0.f);
#pragma unroll
    for (int k = 0; k < 16; k++) {
        __stcs(&zbase[k << 8], z);       // STG.E.128.CS [R + k*4096], zeros
    }

    __syncthreads();

    // Phase 2: patches. SSx/SCx index the slice.
#define SSx(i) s_s[(i) - off]
#define SCx(i) s_c[(i) - off]
    const int h = tid >> 6;
    const int j = tid & 63;
    const int k1 = k0 + 16;
    if (h == 0) {
        // row 4j, quad j: .x = cos_{2j}, .z = -sin_{2j}
        if (j >= k0 && j < k1)
            mbase[j << 8] = make_float4(SCx(2 * j), 0.f, -SSx(2 * j), 0.f);
        // row 4j+4, quad j: .z = sin_{2j+1}
        if (j <= 62 && (j + 1) >= k0 && (j + 1) < k1)
            mbase[(j + 1) << 8] = make_float4(0.f, 0.f, SSx(2 * j + 1), 0.f);
    } else if (h == 2) {
        // row 4j+2, quad j: .x = sin_{2j}, .z = cos_{min(2j+1,126)}
        if (j >= k0 && j < k1) {
            int i = 2 * j + 1; if (i > K_ITERS - 1) i = K_ITERS - 1;
            mbase[j << 8] = make_float4(SSx(2 * j), 0.f, SCx(i), 0.f);
        }
        // row 4j-2, quad j: .x = -sin_{2j-1}
        if (j >= 1 && (j - 1) >= k0 && (j - 1) < k1)
            mbase[(j - 1) << 8] = make_float4(-SSx(2 * j - 1), 0.f, 0.f, 0.f);
    }
#undef SSx
#undef SCx
}

extern "C" void kernel_launch(void* const* d_in, const int* in_sizes, int n_in,
                              void* d_out, int out_size) {
    (void)d_in; (void)in_sizes; (void)n_in; (void)out_size;
    rope_kernel<<<8192, 256, 0, 0>>>((float4*)d_out);
}